// round 6
// baseline (speedup 1.0000x reference)
#include <cuda_runtime.h>

// Batched FFT-1024, four-step 32x32, 64 threads (2 warps) per row.
// Per-thread register FFT-16 + lane-pair split-radix combine via shfl_xor(.,1).
// One XOR-swizzled float2 smem transpose per row (conflict-free both directions).

__device__ constexpr int BR4[16] = {0,8,4,12,2,10,6,14,1,9,5,13,3,11,7,15};

// cos(k*pi/16), sin(k*pi/16), k = 0..15  (w32^k = C16[k] - i*S16[k])
__device__ constexpr float C16[16] = {
    1.0f,               0.980785280403230449f, 0.923879532511286756f, 0.831469612302545237f,
    0.707106781186547524f, 0.555570233019602225f, 0.382683432365089772f, 0.195090322016128268f,
    0.0f,              -0.195090322016128268f,-0.382683432365089772f,-0.555570233019602225f,
   -0.707106781186547524f,-0.831469612302545237f,-0.923879532511286756f,-0.980785280403230449f};
__device__ constexpr float S16[16] = {
    0.0f,               0.195090322016128268f, 0.382683432365089772f, 0.555570233019602225f,
    0.707106781186547524f, 0.831469612302545237f, 0.923879532511286756f, 0.980785280403230449f,
    1.0f,               0.980785280403230449f, 0.923879532511286756f, 0.831469612302545237f,
    0.707106781186547524f, 0.555570233019602225f, 0.382683432365089772f, 0.195090322016128268f};

__device__ __forceinline__ float2 cmul(float2 a, float2 b) {
    return make_float2(fmaf(a.x, b.x, -a.y * b.y),
                       fmaf(a.x, b.y,  a.y * b.x));
}

// In-place radix-2 DIF FFT-16 (forward). Natural input; v[i] = X[BR4[i]] on return.
// All twiddles literal immediates; multiply by w32^k = C16[k] - i*S16[k].
__device__ __forceinline__ void fft16_dif(float2 v[16]) {
#pragma unroll
    for (int s = 0; s < 4; ++s) {
        const int half = 8 >> s;
#pragma unroll
        for (int b = 0; b < 16; b += (half << 1)) {
#pragma unroll
            for (int j = 0; j < half; ++j) {
                const int k = j << (s + 1);
                float2 a = v[b + j];
                float2 c = v[b + j + half];
                v[b + j] = make_float2(a.x + c.x, a.y + c.y);
                const float dr = a.x - c.x;
                const float di = a.y - c.y;
                if (k == 0) {
                    v[b + j + half] = make_float2(dr, di);
                } else if (k == 8) {            // w = -i
                    v[b + j + half] = make_float2(di, -dr);
                } else {
                    // (dr + i di)(C - iS) = (dr*C + di*S) + i(di*C - dr*S)
                    v[b + j + half] = make_float2(fmaf(di, S16[k],  dr * C16[k]),
                                                  fmaf(di, C16[k], -(dr * S16[k])));
                }
            }
        }
    }
}

#define ROWS_PER_BLOCK 2
#define THREADS_PER_BLOCK (ROWS_PER_BLOCK * 64)

__global__ void __launch_bounds__(THREADS_PER_BLOCK)
fft1024_batch_kernel(const float2* __restrict__ in, float2* __restrict__ out, int nrows)
{
    // Per-row 32x32 float2 tile, XOR-swizzled for conflict-free 8B access.
    __shared__ float2 sxy[ROWS_PER_BLOCK][1024];

    const int g  = threadIdx.x >> 6;     // row group within block
    const int l  = threadIdx.x & 63;     // lane within row group
    const int cr = l >> 1;               // column c (stage 1) == freq row r (stage 2)
    const int h  = l & 1;                // split-radix half
    const float sg = h ? -1.0f : 1.0f;

    const int row = blockIdx.x * ROWS_PER_BLOCK + g;
    const bool active = (row < nrows);
    const int srow = active ? row : 0;

    const float2* __restrict__ src = in  + (size_t)srow * 1024;
    float2* __restrict__       dst = out + (size_t)srow * 1024;

    // ---- load: a = 2j + h, v[j] = x[64j + 32h + cr]  (full-line coalesced) ----
    float2 v[16];
#pragma unroll
    for (int j = 0; j < 16; ++j) v[j] = __ldcs(src + 64 * j + 32 * h + cr);

    // ---- stage 1: FFT-32 over a, DIT split-radix ----
    fft16_dif(v);

    float2* tile = sxy[g];
    const int gw    = (2 * cr + h + 8 * (cr >> 4)) & 15;   // loop-invariant write swizzle
    const int wbase = cr * 32 + 16 * h;
#pragma unroll
    for (int i = 0; i < 16; ++i) {
        const int k = BR4[i];
        float twx, twy;
        if (k == 0) {
            twx = v[i].x; twy = v[i].y;
        } else {
            // odd-half pre-twiddle by w32^k (immediate forms), select by h
            const float ox = fmaf(v[i].y, S16[k],  v[i].x * C16[k]);
            const float oy = fmaf(v[i].y, C16[k], -(v[i].x * S16[k]));
            twx = h ? ox : v[i].x;
            twy = h ? oy : v[i].y;
        }
        const float px = __shfl_xor_sync(0xffffffffu, twx, 1);
        const float py = __shfl_xor_sync(0xffffffffu, twy, 1);
        // h=0: E + wO ; h=1: E - wO  -> X32[k + 16h] at column cr
        tile[wbase + (k ^ gw)] = make_float2(fmaf(sg, twx, px), fmaf(sg, twy, py));
    }

    // sync only the 2 warps of this row group
    asm volatile("bar.sync %0, 64;" :: "r"(g + 1) : "memory");

    // ---- stage 2: twiddle w1024^{r*n2}, FFT-32 over n2, DIF split-radix ----
    float si, co;
    sincospif(-(float)(cr * h) * (1.0f / 32.0f), &si, &co);   // b = w1024^{16*r*h}
    float2 b = make_float2(co, si);
    sincospif(-(float)cr * (1.0f / 512.0f), &si, &co);        // step = w1024^{r}
    const float2 step = make_float2(co, si);
    const float2 s2 = cmul(step, step);
    const float2 s4 = cmul(s2, s2);

    const int K     = (cr >> 4) + 8 * h;   // read-swizzle constant
    const int rbase = 512 * h;

#pragma unroll
    for (int q = 0; q < 4; ++q) {
        float2 t0 = b;
        float2 t1 = cmul(t0, step);
        float2 t2 = cmul(t1, step);
        float2 t3 = cmul(t2, step);
        b = cmul(b, s4);                    // short quad chain (depth 4 total)
#pragma unroll
        for (int m = 0; m < 4; ++m) {
            const int j  = 4 * q + m;
            const int gr = (2 * j + K) & 15;
            float2 cv = tile[rbase + 32 * j + (cr ^ gr)];
            cv = cmul(cv, (m == 0) ? t0 : (m == 1) ? t1 : (m == 2) ? t2 : t3);
            const float px = __shfl_xor_sync(0xffffffffu, cv.x, 1);
            const float py = __shfl_xor_sync(0xffffffffu, cv.y, 1);
            const float dx = fmaf(sg, cv.x, px);
            const float dy = fmaf(sg, cv.y, py);
            if (j == 0) {
                v[j] = make_float2(dx, dy);
            } else {
                // h=1 post-twiddle by w32^j (immediate forms), select by h
                const float ox = fmaf(dy, S16[j],  dx * C16[j]);
                const float oy = fmaf(dy, C16[j], -(dx * S16[j]));
                v[j].x = h ? ox : dx;
                v[j].y = h ? oy : dy;
            }
        }
    }

    fft16_dif(v);

    // ---- store: out index = cr + 32h + 64*BR4[i]  (full-line coalesced) ----
#pragma unroll
    for (int i = 0; i < 16; ++i) {
        if (active) __stcs(dst + cr + 32 * h + 64 * BR4[i], v[i]);
    }
}

extern "C" void kernel_launch(void* const* d_in, const int* in_sizes, int n_in,
                              void* d_out, int out_size)
{
    const float2* in  = (const float2*)d_in[0];
    float2*       out = (float2*)d_out;
    const int nrows = in_sizes[0] / 2048;   // 2048 floats (1024 complex) per row
    const int grid = (nrows + ROWS_PER_BLOCK - 1) / ROWS_PER_BLOCK;
    fft1024_batch_kernel<<<grid, THREADS_PER_BLOCK>>>(in, out, nrows);
}

// round 8
// speedup vs baseline: 1.0424x; 1.0424x over previous
#include <cuda_runtime.h>

// Batched FFT-1024, four-step 32x32, 64 threads (2 warps) per row.
// Per-thread register FFT-16 + lane-pair split-radix combine via shfl_xor(.,1).
// One XOR-swizzled float2 smem transpose per row (conflict-free both directions).
// R6: plain __syncthreads() (named barriers reserve extra HW barrier slots per CTA
// and capped residency at ~22% in R5).

__device__ constexpr int BR4[16] = {0,8,4,12,2,10,6,14,1,9,5,13,3,11,7,15};

// cos(k*pi/16), sin(k*pi/16), k = 0..15  (w32^k = C16[k] - i*S16[k])
__device__ constexpr float C16[16] = {
    1.0f,               0.980785280403230449f, 0.923879532511286756f, 0.831469612302545237f,
    0.707106781186547524f, 0.555570233019602225f, 0.382683432365089772f, 0.195090322016128268f,
    0.0f,              -0.195090322016128268f,-0.382683432365089772f,-0.555570233019602225f,
   -0.707106781186547524f,-0.831469612302545237f,-0.923879532511286756f,-0.980785280403230449f};
__device__ constexpr float S16[16] = {
    0.0f,               0.195090322016128268f, 0.382683432365089772f, 0.555570233019602225f,
    0.707106781186547524f, 0.831469612302545237f, 0.923879532511286756f, 0.980785280403230449f,
    1.0f,               0.980785280403230449f, 0.923879532511286756f, 0.831469612302545237f,
    0.707106781186547524f, 0.555570233019602225f, 0.382683432365089772f, 0.195090322016128268f};

__device__ __forceinline__ float2 cmul(float2 a, float2 b) {
    return make_float2(fmaf(a.x, b.x, -a.y * b.y),
                       fmaf(a.x, b.y,  a.y * b.x));
}

// In-place radix-2 DIF FFT-16 (forward). Natural input; v[i] = X[BR4[i]] on return.
// All twiddles literal immediates; multiply by w32^k = C16[k] - i*S16[k].
__device__ __forceinline__ void fft16_dif(float2 v[16]) {
#pragma unroll
    for (int s = 0; s < 4; ++s) {
        const int half = 8 >> s;
#pragma unroll
        for (int b = 0; b < 16; b += (half << 1)) {
#pragma unroll
            for (int j = 0; j < half; ++j) {
                const int k = j << (s + 1);
                float2 a = v[b + j];
                float2 c = v[b + j + half];
                v[b + j] = make_float2(a.x + c.x, a.y + c.y);
                const float dr = a.x - c.x;
                const float di = a.y - c.y;
                if (k == 0) {
                    v[b + j + half] = make_float2(dr, di);
                } else if (k == 8) {            // w = -i
                    v[b + j + half] = make_float2(di, -dr);
                } else {
                    // (dr + i di)(C - iS) = (dr*C + di*S) + i(di*C - dr*S)
                    v[b + j + half] = make_float2(fmaf(di, S16[k],  dr * C16[k]),
                                                  fmaf(di, C16[k], -(dr * S16[k])));
                }
            }
        }
    }
}

#define ROWS_PER_BLOCK 2
#define THREADS_PER_BLOCK (ROWS_PER_BLOCK * 64)

__global__ void __launch_bounds__(THREADS_PER_BLOCK)
fft1024_batch_kernel(const float2* __restrict__ in, float2* __restrict__ out, int nrows)
{
    // Per-row 32x32 float2 tile, XOR-swizzled for conflict-free 8B access.
    __shared__ float2 sxy[ROWS_PER_BLOCK][1024];

    const int g  = threadIdx.x >> 6;     // row group within block
    const int l  = threadIdx.x & 63;     // lane within row group
    const int cr = l >> 1;               // column c (stage 1) == freq row r (stage 2)
    const int h  = l & 1;                // split-radix half
    const float sg = h ? -1.0f : 1.0f;

    const int row = blockIdx.x * ROWS_PER_BLOCK + g;
    const bool active = (row < nrows);
    const int srow = active ? row : 0;

    const float2* __restrict__ src = in  + (size_t)srow * 1024;
    float2* __restrict__       dst = out + (size_t)srow * 1024;

    // ---- load: a = 2j + h, v[j] = x[64j + 32h + cr]  (full-line coalesced) ----
    float2 v[16];
#pragma unroll
    for (int j = 0; j < 16; ++j) v[j] = __ldcs(src + 64 * j + 32 * h + cr);

    // ---- stage 1: FFT-32 over a, DIT split-radix ----
    fft16_dif(v);

    float2* tile = sxy[g];
    const int gw    = (2 * cr + h + 8 * (cr >> 4)) & 15;   // loop-invariant write swizzle
    const int wbase = cr * 32 + 16 * h;
#pragma unroll
    for (int i = 0; i < 16; ++i) {
        const int k = BR4[i];
        float twx, twy;
        if (k == 0) {
            twx = v[i].x; twy = v[i].y;
        } else {
            // odd-half pre-twiddle by w32^k (immediate forms), select by h
            const float ox = fmaf(v[i].y, S16[k],  v[i].x * C16[k]);
            const float oy = fmaf(v[i].y, C16[k], -(v[i].x * S16[k]));
            twx = h ? ox : v[i].x;
            twy = h ? oy : v[i].y;
        }
        const float px = __shfl_xor_sync(0xffffffffu, twx, 1);
        const float py = __shfl_xor_sync(0xffffffffu, twy, 1);
        // h=0: E + wO ; h=1: E - wO  -> X32[k + 16h] at column cr
        tile[wbase + (k ^ gw)] = make_float2(fmaf(sg, twx, px), fmaf(sg, twy, py));
    }

    __syncthreads();

    // ---- stage 2: twiddle w1024^{r*n2}, FFT-32 over n2, DIF split-radix ----
    float si, co;
    sincospif(-(float)(cr * h) * (1.0f / 32.0f), &si, &co);   // b = w1024^{16*r*h}
    float2 b = make_float2(co, si);
    sincospif(-(float)cr * (1.0f / 512.0f), &si, &co);        // step = w1024^{r}
    const float2 step = make_float2(co, si);
    const float2 s2 = cmul(step, step);
    const float2 s4 = cmul(s2, s2);

    const int K     = (cr >> 4) + 8 * h;   // read-swizzle constant
    const int rbase = 512 * h;

#pragma unroll
    for (int q = 0; q < 4; ++q) {
        float2 t0 = b;
        float2 t1 = cmul(t0, step);
        float2 t2 = cmul(t1, step);
        float2 t3 = cmul(t2, step);
        b = cmul(b, s4);                    // short quad chain (depth 4 total)
#pragma unroll
        for (int m = 0; m < 4; ++m) {
            const int j  = 4 * q + m;
            const int gr = (2 * j + K) & 15;
            float2 cv = tile[rbase + 32 * j + (cr ^ gr)];
            cv = cmul(cv, (m == 0) ? t0 : (m == 1) ? t1 : (m == 2) ? t2 : t3);
            const float px = __shfl_xor_sync(0xffffffffu, cv.x, 1);
            const float py = __shfl_xor_sync(0xffffffffu, cv.y, 1);
            const float dx = fmaf(sg, cv.x, px);
            const float dy = fmaf(sg, cv.y, py);
            if (j == 0) {
                v[j] = make_float2(dx, dy);
            } else {
                // h=1 post-twiddle by w32^j (immediate forms), select by h
                const float ox = fmaf(dy, S16[j],  dx * C16[j]);
                const float oy = fmaf(dy, C16[j], -(dx * S16[j]));
                v[j].x = h ? ox : dx;
                v[j].y = h ? oy : dy;
            }
        }
    }

    fft16_dif(v);

    // ---- store: out index = cr + 32h + 64*BR4[i]  (full-line coalesced) ----
#pragma unroll
    for (int i = 0; i < 16; ++i) {
        if (active) __stcs(dst + cr + 32 * h + 64 * BR4[i], v[i]);
    }
}

extern "C" void kernel_launch(void* const* d_in, const int* in_sizes, int n_in,
                              void* d_out, int out_size)
{
    const float2* in  = (const float2*)d_in[0];
    float2*       out = (float2*)d_out;
    const int nrows = in_sizes[0] / 2048;   // 2048 floats (1024 complex) per row
    const int grid = (nrows + ROWS_PER_BLOCK - 1) / ROWS_PER_BLOCK;
    fft1024_batch_kernel<<<grid, THREADS_PER_BLOCK>>>(in, out, nrows);
}

// round 12
// speedup vs baseline: 1.0516x; 1.0088x over previous
#include <cuda_runtime.h>

// Batched FFT-1024, four-step 32x32, 64 threads (2 warps) per row.
// Per-thread register FFT-16 + lane-pair split-radix combine via shfl_xor(.,1).
// One XOR-swizzled float2 smem transpose per row (conflict-free both directions).
// R6: plain __syncthreads() (named barriers reserve extra HW barrier slots per CTA
// and capped residency at ~22% in R5).

__device__ constexpr int BR4[16] = {0,8,4,12,2,10,6,14,1,9,5,13,3,11,7,15};

// cos(k*pi/16), sin(k*pi/16), k = 0..15  (w32^k = C16[k] - i*S16[k])
__device__ constexpr float C16[16] = {
    1.0f,               0.980785280403230449f, 0.923879532511286756f, 0.831469612302545237f,
    0.707106781186547524f, 0.555570233019602225f, 0.382683432365089772f, 0.195090322016128268f,
    0.0f,              -0.195090322016128268f,-0.382683432365089772f,-0.555570233019602225f,
   -0.707106781186547524f,-0.831469612302545237f,-0.923879532511286756f,-0.980785280403230449f};
__device__ constexpr float S16[16] = {
    0.0f,               0.195090322016128268f, 0.382683432365089772f, 0.555570233019602225f,
    0.707106781186547524f, 0.831469612302545237f, 0.923879532511286756f, 0.980785280403230449f,
    1.0f,               0.980785280403230449f, 0.923879532511286756f, 0.831469612302545237f,
    0.707106781186547524f, 0.555570233019602225f, 0.382683432365089772f, 0.195090322016128268f};

__device__ __forceinline__ float2 cmul(float2 a, float2 b) {
    return make_float2(fmaf(a.x, b.x, -a.y * b.y),
                       fmaf(a.x, b.y,  a.y * b.x));
}

// In-place radix-2 DIF FFT-16 (forward). Natural input; v[i] = X[BR4[i]] on return.
// All twiddles literal immediates; multiply by w32^k = C16[k] - i*S16[k].
__device__ __forceinline__ void fft16_dif(float2 v[16]) {
#pragma unroll
    for (int s = 0; s < 4; ++s) {
        const int half = 8 >> s;
#pragma unroll
        for (int b = 0; b < 16; b += (half << 1)) {
#pragma unroll
            for (int j = 0; j < half; ++j) {
                const int k = j << (s + 1);
                float2 a = v[b + j];
                float2 c = v[b + j + half];
                v[b + j] = make_float2(a.x + c.x, a.y + c.y);
                const float dr = a.x - c.x;
                const float di = a.y - c.y;
                if (k == 0) {
                    v[b + j + half] = make_float2(dr, di);
                } else if (k == 8) {            // w = -i
                    v[b + j + half] = make_float2(di, -dr);
                } else {
                    // (dr + i di)(C - iS) = (dr*C + di*S) + i(di*C - dr*S)
                    v[b + j + half] = make_float2(fmaf(di, S16[k],  dr * C16[k]),
                                                  fmaf(di, C16[k], -(dr * S16[k])));
                }
            }
        }
    }
}

#define ROWS_PER_BLOCK 2
#define THREADS_PER_BLOCK (ROWS_PER_BLOCK * 64)

__global__ void __launch_bounds__(THREADS_PER_BLOCK)
fft1024_batch_kernel(const float2* __restrict__ in, float2* __restrict__ out, int nrows)
{
    // Per-row 32x32 float2 tile, XOR-swizzled for conflict-free 8B access.
    __shared__ float2 sxy[ROWS_PER_BLOCK][1024];

    const int g  = threadIdx.x >> 6;     // row group within block
    const int l  = threadIdx.x & 63;     // lane within row group
    const int cr = l >> 1;               // column c (stage 1) == freq row r (stage 2)
    const int h  = l & 1;                // split-radix half
    const float sg = h ? -1.0f : 1.0f;

    const int row = blockIdx.x * ROWS_PER_BLOCK + g;
    const bool active = (row < nrows);
    const int srow = active ? row : 0;

    const float2* __restrict__ src = in  + (size_t)srow * 1024;
    float2* __restrict__       dst = out + (size_t)srow * 1024;

    // ---- load: a = 2j + h, v[j] = x[64j + 32h + cr]  (full-line coalesced) ----
    float2 v[16];
#pragma unroll
    for (int j = 0; j < 16; ++j) v[j] = __ldcs(src + 64 * j + 32 * h + cr);

    // ---- stage 1: FFT-32 over a, DIT split-radix ----
    fft16_dif(v);

    float2* tile = sxy[g];
    const int gw    = (2 * cr + h + 8 * (cr >> 4)) & 15;   // loop-invariant write swizzle
    const int wbase = cr * 32 + 16 * h;
#pragma unroll
    for (int i = 0; i < 16; ++i) {
        const int k = BR4[i];
        float twx, twy;
        if (k == 0) {
            twx = v[i].x; twy = v[i].y;
        } else {
            // odd-half pre-twiddle by w32^k (immediate forms), select by h
            const float ox = fmaf(v[i].y, S16[k],  v[i].x * C16[k]);
            const float oy = fmaf(v[i].y, C16[k], -(v[i].x * S16[k]));
            twx = h ? ox : v[i].x;
            twy = h ? oy : v[i].y;
        }
        const float px = __shfl_xor_sync(0xffffffffu, twx, 1);
        const float py = __shfl_xor_sync(0xffffffffu, twy, 1);
        // h=0: E + wO ; h=1: E - wO  -> X32[k + 16h] at column cr
        tile[wbase + (k ^ gw)] = make_float2(fmaf(sg, twx, px), fmaf(sg, twy, py));
    }

    __syncthreads();

    // ---- stage 2: twiddle w1024^{r*n2}, FFT-32 over n2, DIF split-radix ----
    float si, co;
    sincospif(-(float)(cr * h) * (1.0f / 32.0f), &si, &co);   // b = w1024^{16*r*h}
    float2 b = make_float2(co, si);
    sincospif(-(float)cr * (1.0f / 512.0f), &si, &co);        // step = w1024^{r}
    const float2 step = make_float2(co, si);
    const float2 s2 = cmul(step, step);
    const float2 s4 = cmul(s2, s2);

    const int K     = (cr >> 4) + 8 * h;   // read-swizzle constant
    const int rbase = 512 * h;

#pragma unroll
    for (int q = 0; q < 4; ++q) {
        float2 t0 = b;
        float2 t1 = cmul(t0, step);
        float2 t2 = cmul(t1, step);
        float2 t3 = cmul(t2, step);
        b = cmul(b, s4);                    // short quad chain (depth 4 total)
#pragma unroll
        for (int m = 0; m < 4; ++m) {
            const int j  = 4 * q + m;
            const int gr = (2 * j + K) & 15;
            float2 cv = tile[rbase + 32 * j + (cr ^ gr)];
            cv = cmul(cv, (m == 0) ? t0 : (m == 1) ? t1 : (m == 2) ? t2 : t3);
            const float px = __shfl_xor_sync(0xffffffffu, cv.x, 1);
            const float py = __shfl_xor_sync(0xffffffffu, cv.y, 1);
            const float dx = fmaf(sg, cv.x, px);
            const float dy = fmaf(sg, cv.y, py);
            if (j == 0) {
                v[j] = make_float2(dx, dy);
            } else {
                // h=1 post-twiddle by w32^j (immediate forms), select by h
                const float ox = fmaf(dy, S16[j],  dx * C16[j]);
                const float oy = fmaf(dy, C16[j], -(dx * S16[j]));
                v[j].x = h ? ox : dx;
                v[j].y = h ? oy : dy;
            }
        }
    }

    fft16_dif(v);

    // ---- store: out index = cr + 32h + 64*BR4[i]  (full-line coalesced) ----
#pragma unroll
    for (int i = 0; i < 16; ++i) {
        if (active) __stcs(dst + cr + 32 * h + 64 * BR4[i], v[i]);
    }
}

extern "C" void kernel_launch(void* const* d_in, const int* in_sizes, int n_in,
                              void* d_out, int out_size)
{
    const float2* in  = (const float2*)d_in[0];
    float2*       out = (float2*)d_out;
    const int nrows = in_sizes[0] / 2048;   // 2048 floats (1024 complex) per row
    const int grid = (nrows + ROWS_PER_BLOCK - 1) / ROWS_PER_BLOCK;
    fft1024_batch_kernel<<<grid, THREADS_PER_BLOCK>>>(in, out, nrows);
}